// round 3
// baseline (speedup 1.0000x reference)
#include <cuda_runtime.h>
#include <cstdint>

#define T_STEPS 64
#define BB      8
#define IN_DIM  256
#define HH      512
#define H3      1536
#define NBLK    128
#define NTHR    256

// ---------------- output offsets (floats) ----------------
#define OUT_V      0ull
#define OUT_H      4096ull
#define OUT_DUF    8192ull
#define OUT_TEF    2105344ull
#define OUT_TEMAT  2109440ull
#define OUT_OUTS   4206592ull
#define OUT_DUS    4468736ull
#define OUT_MODS   138686464ull
#define OUT_SS     138735616ull
#define OUT_MS     138736128ull
#define OUT_RS     138736640ull

// ---------------- smem layout (float index) ----------------
#define S_H    0        /* [8][512] h_t (float4-aligned) */
#define S_PRE  4096     /* [1536] */
#define S_NH   5632     /* [512] */
#define S_MOD  6144     /* [128] */
#define S_SCAL 6272     /* s[0..7], m[8..15] */
#define S_BT   6288     /* r,s,m scalars */
#define S_FW   6296     /* fw[il*8+b], 32 */
#define S_FWP  6328     /* [32][8] */
#define S_RED  6584     /* [16] */
#define S_HFWI 6600     /* [32] */
#define S_TEOI 6632     /* [32] */
#define S_TOTF 6664
// prologue overlay: sX [0,1024) + wtile [1024, 14848)
#define SMEM_FLOATS 14848

// ---------------- device globals ----------------
__device__ float    g_wx[T_STEPS * BB * H3];
__device__ float    g_wh[BB * H3];
__device__ float    g_h[BB * HH];
__device__ float    g_hfw[BB * HH];
__device__ float    g_te1[BB * HH];
__device__ float    g_sm[16];
__device__ unsigned g_flagA[NBLK];
__device__ unsigned g_flagB[BB];

// ---------------- helpers ----------------
__device__ __forceinline__ unsigned ld_acq(const unsigned* p) {
    unsigned v;
    asm volatile("ld.global.acquire.gpu.b32 %0, [%1];" : "=r"(v) : "l"(p) : "memory");
    return v;
}
// All threads participate. Poll nflags flags until all >= tgt.
__device__ __forceinline__ void wait_flags(unsigned* flags, int nflags, unsigned tgt) {
    for (;;) {
        int ok = 1;
        if (threadIdx.x < nflags) ok = (ld_acq(&flags[threadIdx.x]) >= tgt);
        if (__syncthreads_count(ok) == NTHR) return;
    }
}
__device__ __forceinline__ void publish(unsigned* slot, unsigned v) {
    __syncthreads();
    if (threadIdx.x == 0) {
        __threadfence();
        atomicExch(slot, v);
    }
}
__device__ __forceinline__ float sigm(float x) { return 1.f / (1.f + __expf(-x)); }
__device__ __forceinline__ float dot4(float4 a, float4 b) {
    return fmaf(a.x, b.x, fmaf(a.y, b.y, fmaf(a.z, b.z, a.w * b.w)));
}
__device__ __forceinline__ void block_sum2(float& a, float& b, float* sRed) {
#pragma unroll
    for (int o = 16; o; o >>= 1) {
        a += __shfl_down_sync(0xffffffffu, a, o);
        b += __shfl_down_sync(0xffffffffu, b, o);
    }
    __syncthreads();
    if ((threadIdx.x & 31) == 0) {
        sRed[threadIdx.x >> 5]     = a;
        sRed[8 + (threadIdx.x >> 5)] = b;
    }
    __syncthreads();
    float ra = 0.f, rb = 0.f;
#pragma unroll
    for (int w = 0; w < 8; w++) { ra += sRed[w]; rb += sRed[8 + w]; }
    a = ra; b = rb;
}

__global__ void zero_flags_kernel() {
    int t = threadIdx.x;
    if (t < NBLK) g_flagA[t] = 0u;
    if (t < BB)   g_flagB[t] = 0u;
}

// ====================================================================
__global__ void __launch_bounds__(NTHR, 1)
sgru_main(const float* __restrict__ x,       const float* __restrict__ h_in,
          const float* __restrict__ v_in,    const float* __restrict__ dU_in,
          const float* __restrict__ te_in,   const float* __restrict__ tE_in,
          const float* __restrict__ x2h_w,   const float* __restrict__ x2h_b,
          const float* __restrict__ h2h_w,   const float* __restrict__ h2h_b,
          const float* __restrict__ lnx_g,   const float* __restrict__ lnx_b,
          const float* __restrict__ lnh_g,   const float* __restrict__ lnh_b,
          const float* __restrict__ h2mod_w, const float* __restrict__ h2mod_b,
          const float* __restrict__ m2r_w,   const float* __restrict__ m2r_b,
          const float* __restrict__ m2s_w,   const float* __restrict__ m2s_b,
          const float* __restrict__ m2m_w,   const float* __restrict__ m2m_b,
          const float* __restrict__ alpha_p, const float* __restrict__ tauU_p,
          float* __restrict__ out)
{
    extern __shared__ float sm[];
    const int tid = threadIdx.x;
    const int bk  = blockIdx.x;
    const int wid = tid >> 5, lid = tid & 31;
    const int i0  = bk * 4;
    const int j0  = 2 * tid;

    float* sH    = sm + S_H;
    float* sPre  = sm + S_PRE;
    float* sNH   = sm + S_NH;
    float* sMod  = sm + S_MOD;
    float* sScal = sm + S_SCAL;
    float* sBt   = sm + S_BT;
    float* sFw   = sm + S_FW;
    float* sFwP  = sm + S_FWP;
    float* sRed  = sm + S_RED;
    float* sHfwI = sm + S_HFWI;
    float* sTeoI = sm + S_TEOI;

    const float spa     = log1pf(expf(alpha_p[0]));
    const float inv_spe = 1.f / (spa + 1e-8f);
    const float tau     = 1.f / (1.f + expf(-tauU_p[0]));
    const float omtau   = 1.f - tau;

    float* tebuf0 = out + OUT_TEF;   // parity-0 buffer == final te output
    float* tebuf1 = g_te1;

    // ================= PROLOGUE: Wx = LN(x @ x2h^T + b) =================
    {
        float* sX    = sm;           // [4][256]
        float* wtile = sm + 1024;    // [1536][9] padded
        const int rg0 = bk * 4;

        float acc[4][6];
#pragma unroll
        for (int r = 0; r < 4; r++)
#pragma unroll
            for (int q = 0; q < 6; q++) acc[r][q] = 0.f;

        for (int idx = tid; idx < 4 * IN_DIM; idx += NTHR)
            sX[idx] = x[(size_t)rg0 * IN_DIM + idx];

        for (int ct = 0; ct < 32; ++ct) {
            const int c0 = ct * 8;
            __syncthreads();
            for (int idx = tid; idx < H3 * 8; idx += NTHR) {
                int kl = idx >> 3, c = idx & 7;
                wtile[kl * 9 + c] = x2h_w[(size_t)kl * IN_DIM + c0 + c];
            }
            __syncthreads();
            float xv[4][8];
#pragma unroll
            for (int r = 0; r < 4; r++)
#pragma unroll
                for (int c = 0; c < 8; c++) xv[r][c] = sX[r * IN_DIM + c0 + c];
#pragma unroll
            for (int q = 0; q < 6; q++) {
                const int kk = tid + 256 * q;
                float wv[8];
#pragma unroll
                for (int c = 0; c < 8; c++) wv[c] = wtile[kk * 9 + c];
#pragma unroll
                for (int r = 0; r < 4; r++)
#pragma unroll
                    for (int c = 0; c < 8; c++)
                        acc[r][q] = fmaf(wv[c], xv[r][c], acc[r][q]);
            }
        }
        float bq[6], lg[6], lb[6];
#pragma unroll
        for (int q = 0; q < 6; q++) {
            int kk = tid + 256 * q;
            bq[q] = x2h_b[kk]; lg[q] = lnx_g[kk]; lb[q] = lnx_b[kk];
        }
#pragma unroll
        for (int r = 0; r < 4; r++)
#pragma unroll
            for (int q = 0; q < 6; q++) acc[r][q] += bq[q];
#pragma unroll
        for (int r = 0; r < 4; r++) {
            float s1 = 0.f, s2 = 0.f;
#pragma unroll
            for (int q = 0; q < 6; q++) { float v = acc[r][q]; s1 += v; s2 = fmaf(v, v, s2); }
            block_sum2(s1, s2, sRed);
            const float mu   = s1 * (1.f / H3);
            const float rstd = rsqrtf(s2 * (1.f / H3) - mu * mu + 1e-5f);
            float* wrow = g_wx + (size_t)(rg0 + r) * H3;
#pragma unroll
            for (int q = 0; q < 6; q++) {
                int kk = tid + 256 * q;
                wrow[kk] = (acc[r][q] - mu) * rstd * lg[q] + lb[q];
            }
        }
        __syncthreads();
    }

    // ================= PROLOGUE: persistent state =================
    float rTE[64], rDU[64], rUp[8], rLo[8];
#pragma unroll
    for (int il = 0; il < 4; ++il) {
        const float* wr = h2h_w + (size_t)(2 * HH + i0 + il) * HH;
        float2 w2 = *(const float2*)&wr[j0];
        rUp[il * 2 + 0] =  fmaxf(1.f - w2.x, 0.f) * inv_spe;
        rUp[il * 2 + 1] =  fmaxf(1.f - w2.y, 0.f) * inv_spe;
        rLo[il * 2 + 0] = -fmaxf(1.f + w2.x, 0.f) * inv_spe;
        rLo[il * 2 + 1] = -fmaxf(1.f + w2.y, 0.f) * inv_spe;
#pragma unroll
        for (int b = 0; b < 8; b++) {
            const int row = il * 8 + b;
            const size_t g = ((size_t)(b * HH + i0 + il)) * HH + j0;
            float2 t2 = *(const float2*)&tE_in[g];
            float2 d2 = *(const float2*)&dU_in[g];
            rTE[row * 2] = t2.x; rTE[row * 2 + 1] = t2.y;
            rDU[row * 2] = d2.x; rDU[row * 2 + 1] = d2.y;
        }
    }
    for (int idx = tid; idx < BB * HH; idx += NTHR) sH[idx] = h_in[idx];

    float vreg0 = 0.f, vreg1 = 0.f, ter0 = 0.f, ter1 = 0.f;
    if (bk < BB) {
        vreg0 = v_in[bk * HH + tid];
        vreg1 = v_in[bk * HH + tid + 256];
        ter0  = te_in[bk * HH + tid];
        ter1  = te_in[bk * HH + tid + 256];
        tebuf0[bk * HH + tid]       = ter0;
        tebuf0[bk * HH + tid + 256] = ter1;
    }
    __syncthreads();

    // fw_0 = spa * dU_init . h_0
#pragma unroll
    for (int b = 0; b < 8; b++) {
        float2 hh = *(float2*)&sH[b * HH + j0];
#pragma unroll
        for (int il = 0; il < 4; ++il) {
            const int row = il * 8 + b;
            float fwp = rDU[row * 2] * hh.x + rDU[row * 2 + 1] * hh.y;
#pragma unroll
            for (int o = 16; o; o >>= 1) fwp += __shfl_down_sync(0xffffffffu, fwp, o);
            if (lid == 0) sFwP[row * 8 + wid] = fwp;
        }
    }
    __syncthreads();
    if (tid < 32) {
        float a = 0.f;
#pragma unroll
        for (int w = 0; w < 8; w++) a += sFwP[tid * 8 + w];
        sFw[tid] = spa * a;
    }
    __syncthreads();

    // ================= MAIN LOOP =================
    for (int it = 0; it <= T_STEPS; ++it) {
        if (it > 0) {
            wait_flags(g_flagB, BB, (unsigned)it);
            const float* teo_g = ((it - 1) & 1) ? tebuf1 : tebuf0;

            float2 hfj[8], tej[8];
#pragma unroll
            for (int b = 0; b < 8; b++) {
                hfj[b] = __ldcg((const float2*)&g_hfw[b * HH + j0]);
                tej[b] = __ldcg((const float2*)&teo_g[b * HH + j0]);
            }
            for (int idx = tid; idx < (BB * HH) / 4; idx += NTHR)
                ((float4*)sH)[idx] = __ldcg(&((const float4*)g_h)[idx]);
            if (tid < 32) {
                int b = tid & 7, il = tid >> 3;
                sHfwI[tid] = __ldcg(&g_hfw[b * HH + i0 + il]);
                sTeoI[tid] = __ldcg(&teo_g[b * HH + i0 + il]);
            }
            if (tid < 16) sScal[tid] = __ldcg(&g_sm[tid]);
            __syncthreads();

            // ---- trace update (step it-1) + fw partials for step it ----
#pragma unroll
            for (int b = 0; b < 8; b++) {
                const float sb  = sScal[b];
                const float mb  = sScal[8 + b];
                const float oms = 1.f - sb;
                const float tm  = tau * mb;
                const float2 hf  = hfj[b];
                const float2 teo = tej[b];
                const float2 hh  = *(const float2*)&sH[b * HH + j0];
#pragma unroll
                for (int il = 0; il < 4; ++il) {
                    const int row = il * 8 + b;
                    const float hfi = sHfwI[row];
                    const float tei = sTeoI[row];
                    float t0 = oms * rTE[row * 2]     + sb * (hfi * teo.x - tei * hf.x);
                    float t1 = oms * rTE[row * 2 + 1] + sb * (hfi * teo.y - tei * hf.y);
                    rTE[row * 2] = t0; rTE[row * 2 + 1] = t1;
                    float d0 = fmaxf(fminf(omtau * rDU[row * 2]     + tm * t0, rUp[il * 2]),     rLo[il * 2]);
                    float d1 = fmaxf(fminf(omtau * rDU[row * 2 + 1] + tm * t1, rUp[il * 2 + 1]), rLo[il * 2 + 1]);
                    rDU[row * 2] = d0; rDU[row * 2 + 1] = d1;
                    float fwp = d0 * hh.x + d1 * hh.y;
#pragma unroll
                    for (int o = 16; o; o >>= 1) fwp += __shfl_down_sync(0xffffffffu, fwp, o);
                    if (lid == 0) sFwP[row * 8 + wid] = fwp;
                }
            }
            __syncthreads();
            if (tid < 32) {
                float a = 0.f;
#pragma unroll
                for (int w = 0; w < 8; w++) a += sFwP[tid * 8 + w];
                sFw[tid] = spa * a;
            }
            __syncthreads();
        }

        if (it < T_STEPS) {
            // ---- W phase: warp wid owns zo row kA; warps 0-3 also dv row kB ----
            {
                const int kA = bk * 8 + wid;
                const float4* wa = (const float4*)(h2h_w + (size_t)kA * HH) + lid * 4;
                const float4 a0 = wa[0], a1 = wa[1], a2 = wa[2], a3 = wa[3];
                float accA[8];
#pragma unroll
                for (int b = 0; b < 8; b++) {
                    const float4* hb = (const float4*)&sH[b * HH + lid * 16];
                    accA[b] = dot4(a0, hb[0]) + dot4(a1, hb[1]) + dot4(a2, hb[2]) + dot4(a3, hb[3]);
                }
                const float biasA = h2h_b[kA];
#pragma unroll
                for (int b = 0; b < 8; b++) {
                    float v = accA[b];
#pragma unroll
                    for (int o = 16; o; o >>= 1) v += __shfl_xor_sync(0xffffffffu, v, o);
                    if (lid == b) g_wh[b * H3 + kA] = v + biasA;
                }
                if (wid < 4) {
                    const int kB = 2 * HH + bk * 4 + wid;
                    const float4* wb = (const float4*)(h2h_w + (size_t)kB * HH) + lid * 4;
                    const float4 b0 = wb[0], b1 = wb[1], b2 = wb[2], b3 = wb[3];
                    float accB[8];
#pragma unroll
                    for (int b = 0; b < 8; b++) {
                        const float4* hb = (const float4*)&sH[b * HH + lid * 16];
                        accB[b] = dot4(b0, hb[0]) + dot4(b1, hb[1]) + dot4(b2, hb[2]) + dot4(b3, hb[3]);
                    }
                    const float biasB = h2h_b[kB];
#pragma unroll
                    for (int b = 0; b < 8; b++) {
                        float v = accB[b];
#pragma unroll
                        for (int o = 16; o; o >>= 1) v += __shfl_xor_sync(0xffffffffu, v, o);
                        if (lid == b) g_wh[b * H3 + kB] = v + biasB + sFw[wid * 8 + b];
                    }
                }
            }
            publish(&g_flagA[bk], (unsigned)(it + 1));

            if (bk >= BB) {
                // dUs store for step it-1, OFF the critical path
                if (it > 0) {
                    float* dus = out + OUT_DUS + (size_t)(it - 1) * (BB * HH * HH);
#pragma unroll
                    for (int il = 0; il < 4; ++il)
#pragma unroll
                        for (int b = 0; b < 8; b++) {
                            const int row = il * 8 + b;
                            *(float2*)&dus[((size_t)(b * HH + i0 + il)) * HH + j0] =
                                make_float2(rDU[row * 2], rDU[row * 2 + 1]);
                        }
                }
            } else {
                // ---- batch phase: block b = bk ----
                wait_flags(g_flagA, NBLK, (unsigned)(it + 1));
                const int b = bk;
                float whv[6], s1 = 0.f, s2 = 0.f;
#pragma unroll
                for (int q = 0; q < 6; q++) {
                    float v = __ldcg(&g_wh[b * H3 + tid + 256 * q]);
                    whv[q] = v; s1 += v; s2 = fmaf(v, v, s2);
                }
                block_sum2(s1, s2, sRed);
                const float mu   = s1 * (1.f / H3);
                const float rstd = rsqrtf(s2 * (1.f / H3) - mu * mu + 1e-5f);
                const float* wxr = g_wx + (size_t)(it * BB + b) * H3;
#pragma unroll
                for (int q = 0; q < 6; q++) {
                    const int kk = tid + 256 * q;
                    sPre[kk] = (whv[q] - mu) * rstd * lnh_g[kk] + lnh_b[kk] + wxr[kk];
                }
                __syncthreads();
                float hf0, hf1;
                {
                    const float z  = sigm(sPre[tid]);
                    const float o  = sigm(sPre[HH + tid]);
                    const float dv = sPre[2 * HH + tid];
                    vreg0 = (1.f - z) * vreg0 + z * dv;
                    const float nh = fmaxf(vreg0, 0.f);
                    hf0 = o * nh;
                    sNH[tid] = nh;
                    g_h[b * HH + tid]   = nh;
                    g_hfw[b * HH + tid] = hf0;
                    out[OUT_OUTS + (size_t)it * (BB * HH) + b * HH + tid] = nh;
                }
                {
                    const int j = tid + 256;
                    const float z  = sigm(sPre[j]);
                    const float o  = sigm(sPre[HH + j]);
                    const float dv = sPre[2 * HH + j];
                    vreg1 = (1.f - z) * vreg1 + z * dv;
                    const float nh = fmaxf(vreg1, 0.f);
                    hf1 = o * nh;
                    sNH[j] = nh;
                    g_h[b * HH + j]   = nh;
                    g_hfw[b * HH + j] = hf1;
                    out[OUT_OUTS + (size_t)it * (BB * HH) + b * HH + j] = nh;
                }
                __syncthreads();
                // mod = relu(new_h @ h2mod^T + b)
                const float4 n0 = *(const float4*)&sNH[lid * 16];
                const float4 n1 = *(const float4*)&sNH[lid * 16 + 4];
                const float4 n2 = *(const float4*)&sNH[lid * 16 + 8];
                const float4 n3 = *(const float4*)&sNH[lid * 16 + 12];
#pragma unroll
                for (int rep = 0; rep < 12; rep++) {
                    const int row = rep * 8 + wid;
                    const float4* mw = (const float4*)(h2mod_w + (size_t)row * HH) + lid * 4;
                    float a = dot4(mw[0], n0) + dot4(mw[1], n1) + dot4(mw[2], n2) + dot4(mw[3], n3);
#pragma unroll
                    for (int o = 16; o; o >>= 1) a += __shfl_xor_sync(0xffffffffu, a, o);
                    if (lid == 0) {
                        const float mv = fmaxf(a + h2mod_b[row], 0.f);
                        sMod[row] = mv;
                        out[OUT_MODS + (size_t)it * (BB * 96) + b * 96 + row] = mv;
                    }
                }
                __syncthreads();
                if (wid < 3) {
                    const float* ww = (wid == 0) ? m2r_w : (wid == 1) ? m2s_w : m2m_w;
                    float a = sMod[wid * 32 + lid] * ww[lid];
#pragma unroll
                    for (int o = 16; o; o >>= 1) a += __shfl_xor_sync(0xffffffffu, a, o);
                    if (lid == 0) {
                        if (wid == 0) {
                            const float r = sigm(a + m2r_b[0]);
                            sBt[0] = r;
                            out[OUT_RS + (size_t)it * BB + b] = r;
                        } else if (wid == 1) {
                            const float s = sigm(a + m2s_b[0]);
                            sBt[1] = s; g_sm[b] = s;
                            out[OUT_SS + (size_t)it * BB + b] = s;
                        } else {
                            const float mmv = a + m2m_b[0];
                            const float m = mmv - tanhf(mmv);
                            sBt[2] = m; g_sm[8 + b] = m;
                            out[OUT_MS + (size_t)it * BB + b] = m;
                        }
                    }
                }
                __syncthreads();
                const float r = sBt[0];
                float* tnb = (it & 1) ? tebuf0 : tebuf1;
                ter0 = (1.f - r) * ter0 + r * hf0;
                ter1 = (1.f - r) * ter1 + r * hf1;
                tnb[b * HH + tid]       = ter0;
                tnb[b * HH + tid + 256] = ter1;
                publish(&g_flagB[bk], (unsigned)(it + 1));
                if (it > 0) {
                    float* dus = out + OUT_DUS + (size_t)(it - 1) * (BB * HH * HH);
#pragma unroll
                    for (int il = 0; il < 4; ++il)
#pragma unroll
                        for (int bb = 0; bb < 8; bb++) {
                            const int row = il * 8 + bb;
                            *(float2*)&dus[((size_t)(bb * HH + i0 + il)) * HH + j0] =
                                make_float2(rDU[row * 2], rDU[row * 2 + 1]);
                        }
                }
            }
        } else {
            // final dUs slice (step T-1)
            float* dus = out + OUT_DUS + (size_t)(T_STEPS - 1) * (BB * HH * HH);
#pragma unroll
            for (int il = 0; il < 4; ++il)
#pragma unroll
                for (int b = 0; b < 8; b++) {
                    const int row = il * 8 + b;
                    *(float2*)&dus[((size_t)(b * HH + i0 + il)) * HH + j0] =
                        make_float2(rDU[row * 2], rDU[row * 2 + 1]);
                }
        }
    }

    // ================= EPILOGUE =================
#pragma unroll
    for (int il = 0; il < 4; ++il)
#pragma unroll
        for (int b = 0; b < 8; b++) {
            const int row = il * 8 + b;
            const size_t g = ((size_t)(b * HH + i0 + il)) * HH + j0;
            *(float2*)&out[OUT_TEMAT + g] = make_float2(rTE[row * 2], rTE[row * 2 + 1]);
            *(float2*)&out[OUT_DUF  + g] = make_float2(rDU[row * 2], rDU[row * 2 + 1]);
        }
    if (bk < BB) {
        out[OUT_V + bk * HH + tid]       = vreg0;
        out[OUT_V + bk * HH + tid + 256] = vreg1;
        out[OUT_H + bk * HH + tid]       = sH[bk * HH + tid];
        out[OUT_H + bk * HH + tid + 256] = sH[bk * HH + tid + 256];
    }
}

// ====================================================================
extern "C" void kernel_launch(void* const* d_in, const int* in_sizes, int n_in,
                              void* d_out, int out_size) {
    const float* x       = (const float*)d_in[0];
    const float* h       = (const float*)d_in[1];
    const float* v       = (const float*)d_in[2];
    const float* dU      = (const float*)d_in[3];
    const float* te      = (const float*)d_in[4];
    const float* tE      = (const float*)d_in[5];
    const float* x2h_w   = (const float*)d_in[6];
    const float* x2h_b   = (const float*)d_in[7];
    const float* h2h_w   = (const float*)d_in[8];
    const float* h2h_b   = (const float*)d_in[9];
    const float* lnx_g   = (const float*)d_in[10];
    const float* lnx_b   = (const float*)d_in[11];
    const float* lnh_g   = (const float*)d_in[12];
    const float* lnh_b   = (const float*)d_in[13];
    const float* h2mod_w = (const float*)d_in[14];
    const float* h2mod_b = (const float*)d_in[15];
    const float* m2r_w   = (const float*)d_in[16];
    const float* m2r_b   = (const float*)d_in[17];
    const float* m2s_w   = (const float*)d_in[18];
    const float* m2s_b   = (const float*)d_in[19];
    const float* m2m_w   = (const float*)d_in[20];
    const float* m2m_b   = (const float*)d_in[21];
    const float* alpha   = (const float*)d_in[22];
    const float* tauU    = (const float*)d_in[23];
    float* out = (float*)d_out;

    const size_t smem = (size_t)SMEM_FLOATS * sizeof(float);
    cudaFuncSetAttribute(sgru_main, cudaFuncAttributeMaxDynamicSharedMemorySize, (int)smem);

    zero_flags_kernel<<<1, 128>>>();
    sgru_main<<<NBLK, NTHR, smem>>>(x, h, v, dU, te, tE,
                                    x2h_w, x2h_b, h2h_w, h2h_b,
                                    lnx_g, lnx_b, lnh_g, lnh_b,
                                    h2mod_w, h2mod_b,
                                    m2r_w, m2r_b, m2s_w, m2s_b, m2m_w, m2m_b,
                                    alpha, tauU, out);
}

// round 4
// speedup vs baseline: 1.1172x; 1.1172x over previous
#include <cuda_runtime.h>
#include <cstdint>

#define T_STEPS 64
#define BB      8
#define IN_DIM  256
#define HH      512
#define H3      1536
#define NBLK    128
#define NTHR    512

// ---------------- output offsets (floats) ----------------
#define OUT_V      0ull
#define OUT_H      4096ull
#define OUT_DUF    8192ull
#define OUT_TEF    2105344ull
#define OUT_TEMAT  2109440ull
#define OUT_OUTS   4206592ull
#define OUT_DUS    4468736ull
#define OUT_MODS   138686464ull
#define OUT_SS     138735616ull
#define OUT_MS     138736128ull
#define OUT_RS     138736640ull

// ---------------- smem layout (float index) ----------------
#define S_WH   0        /* [8][1536] */
#define S_WX   12288    /* [8][1536] */
#define S_H    24576    /* [8][512]  */
#define S_HFW  28672    /* [8][512]  */
#define S_TE   32768    /* [8][512]  */
#define S_UP   36864    /* [4][512]  */
#define S_LO   38912    /* [4][512]  */
#define S_FWP  40960    /* [32][16]  */
#define S_FW   41472    /* [32]      */
#define S_MOD  41504    /* [96] pad  */
#define S_SCAL 41600    /* r[8] s[8] m[8] */
#define S_RED  41632    /* [32]      */
#define S_MU   41664    /* [8]       */
#define S_RS   41672    /* [8]       */
#define SMEM_FLOATS 41680
// prologue overlay: sX [0,1024) + wtile [1024, 14848)  (inside S_WH/S_WX region)

// ---------------- device globals ----------------
__device__ float    g_wx[T_STEPS * BB * H3];
__device__ float    g_whbuf[2][BB * H3];
__device__ float    g_sm3[24];           // r[8], s[8], m[8]
__device__ unsigned g_flagA[NBLK];
__device__ unsigned g_flagB[BB];

// ---------------- helpers ----------------
__device__ __forceinline__ unsigned ld_acq(const unsigned* p) {
    unsigned v;
    asm volatile("ld.global.acquire.gpu.b32 %0, [%1];" : "=r"(v) : "l"(p) : "memory");
    return v;
}
__device__ __forceinline__ void st_rel(unsigned* p, unsigned v) {
    asm volatile("st.global.release.gpu.b32 [%0], %1;" :: "l"(p), "r"(v) : "memory");
}
__device__ __forceinline__ void wait_flags(unsigned* flags, int nflags, unsigned tgt) {
    for (;;) {
        int ok = 1;
        if (threadIdx.x < (unsigned)nflags) ok = (ld_acq(&flags[threadIdx.x]) >= tgt);
        if (__syncthreads_count(ok) == NTHR) return;
    }
}
__device__ __forceinline__ void publish(unsigned* slot, unsigned v) {
    __syncthreads();
    if (threadIdx.x == 0) st_rel(slot, v);
}
__device__ __forceinline__ float sigm(float x) { return 1.f / (1.f + __expf(-x)); }
__device__ __forceinline__ float dot4(float4 a, float4 b) {
    return fmaf(a.x, b.x, fmaf(a.y, b.y, fmaf(a.z, b.z, a.w * b.w)));
}
__device__ __forceinline__ float wred(float v) {
#pragma unroll
    for (int o = 16; o; o >>= 1) v += __shfl_down_sync(0xffffffffu, v, o);
    return v;
}
__device__ __forceinline__ float wxor(float v) {
#pragma unroll
    for (int o = 16; o; o >>= 1) v += __shfl_xor_sync(0xffffffffu, v, o);
    return v;
}
__device__ __forceinline__ void block_sum2(float& a, float& b, float* sRed) {
#pragma unroll
    for (int o = 16; o; o >>= 1) {
        a += __shfl_down_sync(0xffffffffu, a, o);
        b += __shfl_down_sync(0xffffffffu, b, o);
    }
    __syncthreads();
    const int w = threadIdx.x >> 5;
    if ((threadIdx.x & 31) == 0) { sRed[w] = a; sRed[16 + w] = b; }
    __syncthreads();
    float ra = 0.f, rb = 0.f;
#pragma unroll
    for (int i = 0; i < 16; i++) { ra += sRed[i]; rb += sRed[16 + i]; }
    a = ra; b = rb;
}

__global__ void zero_flags_kernel() {
    int t = threadIdx.x;
    if (t < NBLK) g_flagA[t] = 0u;
    if (t < BB)   g_flagB[t] = 0u;
}

// ====================================================================
__global__ void __launch_bounds__(NTHR, 1)
sgru_main(const float* __restrict__ x,       const float* __restrict__ h_in,
          const float* __restrict__ v_in,    const float* __restrict__ dU_in,
          const float* __restrict__ te_in,   const float* __restrict__ tE_in,
          const float* __restrict__ x2h_w,   const float* __restrict__ x2h_b,
          const float* __restrict__ h2h_w,   const float* __restrict__ h2h_b,
          const float* __restrict__ lnx_g,   const float* __restrict__ lnx_b,
          const float* __restrict__ lnh_g,   const float* __restrict__ lnh_b,
          const float* __restrict__ h2mod_w, const float* __restrict__ h2mod_b,
          const float* __restrict__ m2r_w,   const float* __restrict__ m2r_b,
          const float* __restrict__ m2s_w,   const float* __restrict__ m2s_b,
          const float* __restrict__ m2m_w,   const float* __restrict__ m2m_b,
          const float* __restrict__ alpha_p, const float* __restrict__ tauU_p,
          float* __restrict__ out)
{
    extern __shared__ float sm[];
    const int tid = threadIdx.x;
    const int bk  = blockIdx.x;
    const int wid = tid >> 5, lid = tid & 31;
    const int i0  = bk * 4;

    float* sWh   = sm + S_WH;
    float* sWx   = sm + S_WX;
    float* sH    = sm + S_H;
    float* sHfw  = sm + S_HFW;
    float* sTe   = sm + S_TE;
    float* sUp   = sm + S_UP;
    float* sLo   = sm + S_LO;
    float* sFwP  = sm + S_FWP;
    float* sFw   = sm + S_FW;
    float* sMod  = sm + S_MOD;
    float* sScal = sm + S_SCAL;
    float* sRed  = sm + S_RED;
    float* sMu   = sm + S_MU;
    float* sRs   = sm + S_RS;

    const float spa     = log1pf(expf(alpha_p[0]));
    const float inv_spe = 1.f / (spa + 1e-8f);
    const float tau     = 1.f / (1.f + expf(-tauU_p[0]));
    const float omtau   = 1.f - tau;

    // ================= PROLOGUE A: g_wx = LN(x @ x2h^T + b) =================
    {
        float* sX    = sm;           // [4][256]
        float* wtile = sm + 1024;    // [1536][9] padded
        const int rg0 = bk * 4;

        float acc[4][3];
#pragma unroll
        for (int r = 0; r < 4; r++)
#pragma unroll
            for (int q = 0; q < 3; q++) acc[r][q] = 0.f;

        for (int idx = tid; idx < 4 * IN_DIM; idx += NTHR)
            sX[idx] = x[(size_t)rg0 * IN_DIM + idx];

        for (int ct = 0; ct < 32; ++ct) {
            const int c0 = ct * 8;
            __syncthreads();
            for (int idx = tid; idx < H3 * 8; idx += NTHR) {
                int kl = idx >> 3, c = idx & 7;
                wtile[kl * 9 + c] = x2h_w[(size_t)kl * IN_DIM + c0 + c];
            }
            __syncthreads();
            float xv[4][8];
#pragma unroll
            for (int r = 0; r < 4; r++)
#pragma unroll
                for (int c = 0; c < 8; c++) xv[r][c] = sX[r * IN_DIM + c0 + c];
#pragma unroll
            for (int q = 0; q < 3; q++) {
                const int kk = tid + NTHR * q;
                float wv[8];
#pragma unroll
                for (int c = 0; c < 8; c++) wv[c] = wtile[kk * 9 + c];
#pragma unroll
                for (int r = 0; r < 4; r++)
#pragma unroll
                    for (int c = 0; c < 8; c++)
                        acc[r][q] = fmaf(wv[c], xv[r][c], acc[r][q]);
            }
        }
#pragma unroll
        for (int q = 0; q < 3; q++) {
            const float bq = x2h_b[tid + NTHR * q];
#pragma unroll
            for (int r = 0; r < 4; r++) acc[r][q] += bq;
        }
#pragma unroll
        for (int r = 0; r < 4; r++) {
            float s1 = 0.f, s2 = 0.f;
#pragma unroll
            for (int q = 0; q < 3; q++) { float v = acc[r][q]; s1 += v; s2 = fmaf(v, v, s2); }
            block_sum2(s1, s2, sRed);
            const float mu   = s1 * (1.f / H3);
            const float rstd = rsqrtf(s2 * (1.f / H3) - mu * mu + 1e-5f);
            float* wrow = g_wx + (size_t)(rg0 + r) * H3;
#pragma unroll
            for (int q = 0; q < 3; q++) {
                const int kk = tid + NTHR * q;
                wrow[kk] = (acc[r][q] - mu) * rstd * lnx_g[kk] + lnx_b[kk];
            }
        }
        __syncthreads();
    }

    // ================= PROLOGUE B: persistent state =================
    float rTE[32], rDU[32], vr[8];
#pragma unroll
    for (int il = 0; il < 4; ++il) {
        const float w = h2h_w[(size_t)(2 * HH + i0 + il) * HH + tid];
        sUp[il * HH + tid] =  fmaxf(1.f - w, 0.f) * inv_spe;
        sLo[il * HH + tid] = -fmaxf(1.f + w, 0.f) * inv_spe;
#pragma unroll
        for (int b = 0; b < 8; b++) {
            const int row = il * 8 + b;
            const size_t g = (size_t)(b * HH + i0 + il) * HH + tid;
            rTE[row] = tE_in[g];
            rDU[row] = dU_in[g];
        }
    }
#pragma unroll
    for (int b = 0; b < 8; b++) {
        vr[b] = v_in[b * HH + tid];
        sTe[b * HH + tid] = te_in[b * HH + tid];
        sH [b * HH + tid] = h_in[b * HH + tid];
    }
    __syncthreads();

    // fw_0 = spa * dU_init . h_0
#pragma unroll
    for (int b = 0; b < 8; b++) {
        const float hh = sH[b * HH + tid];
#pragma unroll
        for (int il = 0; il < 4; ++il) {
            const int row = il * 8 + b;
            float fwp = wred(rDU[row] * hh);
            if (lid == 0) sFwP[row * 16 + wid] = fwp;
        }
    }
    __syncthreads();
    if (tid < 32) {
        float a = 0.f;
#pragma unroll
        for (int w = 0; w < 16; w++) a += sFwP[tid * 16 + w];
        sFw[tid] = spa * a;
    }
    __syncthreads();

    // ================= MAIN LOOP =================
    for (int it = 0; it <= T_STEPS; ++it) {
        if (it > 0) {
            wait_flags(g_flagB, BB, (unsigned)it);
            if (tid < 24) sScal[tid] = __ldcg(&g_sm3[tid]);
            __syncthreads();

            // trace for step it-1 (tE, dU in regs; te advance)
            float tnew[8];
#pragma unroll
            for (int b = 0; b < 8; b++) {
                const float rb  = sScal[b];
                const float sb  = sScal[8 + b];
                const float mb  = sScal[16 + b];
                const float oms = 1.f - sb;
                const float tm  = tau * mb;
                const float teo = sTe [b * HH + tid];
                const float hf  = sHfw[b * HH + tid];
                const float hh  = sH  [b * HH + tid];
#pragma unroll
                for (int il = 0; il < 4; ++il) {
                    const int row = il * 8 + b;
                    const float hfi = sHfw[b * HH + i0 + il];
                    const float tei = sTe [b * HH + i0 + il];
                    const float t = oms * rTE[row] + sb * (hfi * teo - tei * hf);
                    rTE[row] = t;
                    float d = omtau * rDU[row] + tm * t;
                    d = fminf(d, sUp[il * HH + tid]);
                    d = fmaxf(d, sLo[il * HH + tid]);
                    rDU[row] = d;
                    float fwp = wred(d * hh);
                    if (lid == 0) sFwP[row * 16 + wid] = fwp;
                }
                tnew[b] = (1.f - rb) * teo + rb * hf;
            }
            __syncthreads();
            if (tid < 32) {
                float a = 0.f;
#pragma unroll
                for (int w = 0; w < 16; w++) a += sFwP[tid * 16 + w];
                sFw[tid] = spa * a;
            }
#pragma unroll
            for (int b = 0; b < 8; b++) sTe[b * HH + tid] = tnew[b];
            __syncthreads();
        }

        if (it < T_STEPS) {
            float* whb = g_whbuf[it & 1];

            // ---- W phase: 12 warps each compute one Wh row ----
            if (wid < 12) {
                const int k = (wid < 8) ? (bk * 8 + wid) : (2 * HH + bk * 4 + (wid - 8));
                const float4* wr = (const float4*)(h2h_w + (size_t)k * HH);
                float accA[8];
#pragma unroll
                for (int b = 0; b < 8; b++) accA[b] = 0.f;
#pragma unroll
                for (int c = 0; c < 4; c++) {
                    const float4 w4 = wr[lid + 32 * c];
#pragma unroll
                    for (int b = 0; b < 8; b++) {
                        const float4 h4 = *(const float4*)&sH[b * HH + 4 * (lid + 32 * c)];
                        accA[b] += dot4(w4, h4);
                    }
                }
                const float bias = h2h_b[k];
#pragma unroll
                for (int b = 0; b < 8; b++) {
                    float v = wxor(accA[b]);
                    if (lid == b) {
                        float add = bias + ((wid >= 8) ? sFw[(wid - 8) * 8 + b] : 0.f);
                        whb[b * H3 + k] = v + add;
                    }
                }
            }
            publish(&g_flagA[bk], (unsigned)(it + 1));

            // shadow work: prefetch wx, store dUs(it-1)
            {
                const float* wxg = g_wx + (size_t)it * (BB * H3);
                for (int i = tid; i < BB * H3; i += NTHR)
                    sWx[i] = __ldcg(&wxg[i]);
            }
            if (it > 0) {
                float* dus = out + OUT_DUS + (size_t)(it - 1) * (BB * HH * HH);
#pragma unroll
                for (int il = 0; il < 4; ++il)
#pragma unroll
                    for (int b = 0; b < 8; b++)
                        __stcs(&dus[(size_t)(b * HH + i0 + il) * HH + tid], rDU[il * 8 + b]);
            }

            wait_flags(g_flagA, NBLK, (unsigned)(it + 1));
            for (int i = tid; i < BB * H3; i += NTHR)
                sWh[i] = __ldcg(&whb[i]);
            __syncthreads();

            // ---- LN stats: 64 threads per batch ----
            {
                const int bt = tid >> 6, l6 = tid & 63;
                float s1 = 0.f, s2 = 0.f;
#pragma unroll
                for (int q = 0; q < 24; q++) {
                    const float v = sWh[bt * H3 + l6 + 64 * q];
                    s1 += v; s2 = fmaf(v, v, s2);
                }
#pragma unroll
                for (int o = 16; o; o >>= 1) {
                    s1 += __shfl_down_sync(0xffffffffu, s1, o);
                    s2 += __shfl_down_sync(0xffffffffu, s2, o);
                }
                if (lid == 0) { sRed[wid * 2] = s1; sRed[wid * 2 + 1] = s2; }
                __syncthreads();
                if (tid < 8) {
                    const float t1 = sRed[tid * 4] + sRed[tid * 4 + 2];
                    const float t2 = sRed[tid * 4 + 1] + sRed[tid * 4 + 3];
                    const float mu = t1 * (1.f / H3);
                    sMu[tid] = mu;
                    sRs[tid] = rsqrtf(t2 * (1.f / H3) - mu * mu + 1e-5f);
                }
                __syncthreads();
            }

            // ---- gates (redundant, all 8 batches) ----
            {
                const float lg0 = lnh_g[tid],            lb0 = lnh_b[tid];
                const float lg1 = lnh_g[HH + tid],       lb1 = lnh_b[HH + tid];
                const float lg2 = lnh_g[2 * HH + tid],   lb2 = lnh_b[2 * HH + tid];
#pragma unroll
                for (int b = 0; b < 8; b++) {
                    const float mu = sMu[b], rs = sRs[b];
                    const float pz = (sWh[b * H3 + tid]          - mu) * rs * lg0 + lb0 + sWx[b * H3 + tid];
                    const float po = (sWh[b * H3 + HH + tid]     - mu) * rs * lg1 + lb1 + sWx[b * H3 + HH + tid];
                    const float pd = (sWh[b * H3 + 2 * HH + tid] - mu) * rs * lg2 + lb2 + sWx[b * H3 + 2 * HH + tid];
                    const float z = sigm(pz);
                    const float o = sigm(po);
                    vr[b] = (1.f - z) * vr[b] + z * pd;
                    const float nh = fmaxf(vr[b], 0.f);
                    const float hf = o * nh;
                    sH  [b * HH + tid] = nh;
                    sHfw[b * HH + tid] = hf;
                    if (bk == 8 + b)
                        out[OUT_OUTS + (size_t)it * (BB * HH) + b * HH + tid] = nh;
                }
            }
            __syncthreads();

            // ---- scalar phase: blocks 0..7, batch b = bk ----
            if (bk < BB) {
                const int b = bk;
                float4 n4[4];
#pragma unroll
                for (int c = 0; c < 4; c++)
                    n4[c] = *(const float4*)&sH[b * HH + 4 * (lid + 32 * c)];
#pragma unroll
                for (int rr = 0; rr < 6; rr++) {
                    const int row = wid + 16 * rr;
                    const float4* mw = (const float4*)(h2mod_w + (size_t)row * HH);
                    float a = 0.f;
#pragma unroll
                    for (int c = 0; c < 4; c++) a += dot4(mw[lid + 32 * c], n4[c]);
                    a = wxor(a);
                    if (lid == 0) {
                        const float mv = fmaxf(a + h2mod_b[row], 0.f);
                        sMod[row] = mv;
                        out[OUT_MODS + (size_t)it * (BB * 96) + b * 96 + row] = mv;
                    }
                }
                __syncthreads();
                if (wid < 3) {
                    const float* ww = (wid == 0) ? m2r_w : (wid == 1) ? m2s_w : m2m_w;
                    float a = wxor(sMod[wid * 32 + lid] * ww[lid]);
                    if (lid == 0) {
                        if (wid == 0) {
                            const float r = sigm(a + m2r_b[0]);
                            g_sm3[b] = r;
                            out[OUT_RS + (size_t)it * BB + b] = r;
                        } else if (wid == 1) {
                            const float s = sigm(a + m2s_b[0]);
                            g_sm3[8 + b] = s;
                            out[OUT_SS + (size_t)it * BB + b] = s;
                        } else {
                            const float mmv = a + m2m_b[0];
                            const float m = mmv - tanhf(mmv);
                            g_sm3[16 + b] = m;
                            out[OUT_MS + (size_t)it * BB + b] = m;
                        }
                    }
                }
                publish(&g_flagB[bk], (unsigned)(it + 1));
            }
        }
    }

    // ================= EPILOGUE =================
    {
        float* dus63 = out + OUT_DUS + (size_t)(T_STEPS - 1) * (BB * HH * HH);
#pragma unroll
        for (int il = 0; il < 4; ++il)
#pragma unroll
            for (int b = 0; b < 8; b++) {
                const int row = il * 8 + b;
                const size_t g = (size_t)(b * HH + i0 + il) * HH + tid;
                dus63[g] = rDU[row];
                out[OUT_DUF + g]   = rDU[row];
                out[OUT_TEMAT + g] = rTE[row];
            }
    }
    if (bk < BB) {
        out[OUT_V   + bk * HH + tid] = vr[bk];
        out[OUT_H   + bk * HH + tid] = sH[bk * HH + tid];
        out[OUT_TEF + bk * HH + tid] = sTe[bk * HH + tid];
    }
}

// ====================================================================
extern "C" void kernel_launch(void* const* d_in, const int* in_sizes, int n_in,
                              void* d_out, int out_size) {
    const float* x       = (const float*)d_in[0];
    const float* h       = (const float*)d_in[1];
    const float* v       = (const float*)d_in[2];
    const float* dU      = (const float*)d_in[3];
    const float* te      = (const float*)d_in[4];
    const float* tE      = (const float*)d_in[5];
    const float* x2h_w   = (const float*)d_in[6];
    const float* x2h_b   = (const float*)d_in[7];
    const float* h2h_w   = (const float*)d_in[8];
    const float* h2h_b   = (const float*)d_in[9];
    const float* lnx_g   = (const float*)d_in[10];
    const float* lnx_b   = (const float*)d_in[11];
    const float* lnh_g   = (const float*)d_in[12];
    const float* lnh_b   = (const float*)d_in[13];
    const float* h2mod_w = (const float*)d_in[14];
    const float* h2mod_b = (const float*)d_in[15];
    const float* m2r_w   = (const float*)d_in[16];
    const float* m2r_b   = (const float*)d_in[17];
    const float* m2s_w   = (const float*)d_in[18];
    const float* m2s_b   = (const float*)d_in[19];
    const float* m2m_w   = (const float*)d_in[20];
    const float* m2m_b   = (const float*)d_in[21];
    const float* alpha   = (const float*)d_in[22];
    const float* tauU    = (const float*)d_in[23];
    float* out = (float*)d_out;

    const size_t smem = (size_t)SMEM_FLOATS * sizeof(float);
    cudaFuncSetAttribute(sgru_main, cudaFuncAttributeMaxDynamicSharedMemorySize, (int)smem);

    zero_flags_kernel<<<1, 128>>>();
    sgru_main<<<NBLK, NTHR, smem>>>(x, h, v, dU, te, tE,
                                    x2h_w, x2h_b, h2h_w, h2h_b,
                                    lnx_g, lnx_b, lnh_g, lnh_b,
                                    h2mod_w, h2mod_b,
                                    m2r_w, m2r_b, m2s_w, m2s_b, m2m_w, m2m_b,
                                    alpha, tauU, out);
}

// round 5
// speedup vs baseline: 1.1563x; 1.0349x over previous
#include <cuda_runtime.h>
#include <cuda_pipeline.h>
#include <cstdint>

#define T_STEPS 64
#define BB      8
#define IN_DIM  256
#define HH      512
#define H3      1536
#define NBLK    128
#define NTHR    512
#define AGG     127

// ---------------- output offsets (floats) ----------------
#define OUT_V      0ull
#define OUT_H      4096ull
#define OUT_DUF    8192ull
#define OUT_TEF    2105344ull
#define OUT_TEMAT  2109440ull
#define OUT_OUTS   4206592ull
#define OUT_DUS    4468736ull
#define OUT_MODS   138686464ull
#define OUT_SS     138735616ull
#define OUT_MS     138736128ull
#define OUT_RS     138736640ull

// ---------------- smem layout (float index) ----------------
#define S_WH   0        /* [8][1536] */
#define S_WX   12288    /* [8][1536] */
#define S_H    24576    /* [8][512]  */
#define S_HFW  28672    /* [8][512]  */
#define S_TE   32768    /* [8][512]  */
#define S_ZW   36864    /* [8][512] zo weight rows */
#define S_FWP  40960    /* [32][16]  */
#define S_MOD  41472    /* [96] pad 128 */
#define S_SCAL 41600    /* r[8] s[8] m[8] -> 32 */
#define S_RED  41632    /* [32] */
#define S_MU   41664    /* [8] */
#define S_RS   41672    /* [8] */
#define S_BT   41680    /* [8] */
#define SMEM_FLOATS 41688
// prologue overlay: sX [0,1024) + wtile [1024, 14848) inside S_WH/S_WX region

// ---------------- device globals ----------------
__device__ float    g_wx[T_STEPS * BB * H3];
__device__ float    g_whbuf[2][BB * H3];
__device__ unsigned g_lineA[NBLK][32];   // [0]=flag, padded to 128B
__device__ unsigned g_lineB[BB][32];     // [0]=flag, [1..3]=r,s,m bits
__device__ unsigned g_epochA;

// ---------------- helpers ----------------
__device__ __forceinline__ unsigned ld_acq(const unsigned* p) {
    unsigned v;
    asm volatile("ld.global.acquire.gpu.b32 %0, [%1];" : "=r"(v) : "l"(p) : "memory");
    return v;
}
__device__ __forceinline__ void st_rel(unsigned* p, unsigned v) {
    asm volatile("st.global.release.gpu.b32 [%0], %1;" :: "l"(p), "r"(v) : "memory");
}
__device__ __forceinline__ float sigm(float x) { return 1.f / (1.f + __expf(-x)); }
__device__ __forceinline__ float dot4(float4 a, float4 b) {
    return fmaf(a.x, b.x, fmaf(a.y, b.y, fmaf(a.z, b.z, a.w * b.w)));
}
__device__ __forceinline__ float wred(float v) {
#pragma unroll
    for (int o = 16; o; o >>= 1) v += __shfl_down_sync(0xffffffffu, v, o);
    return v;
}
__device__ __forceinline__ float wxor(float v) {
#pragma unroll
    for (int o = 16; o; o >>= 1) v += __shfl_xor_sync(0xffffffffu, v, o);
    return v;
}
__device__ __forceinline__ void block_sum2(float& a, float& b, float* sRed) {
#pragma unroll
    for (int o = 16; o; o >>= 1) {
        a += __shfl_down_sync(0xffffffffu, a, o);
        b += __shfl_down_sync(0xffffffffu, b, o);
    }
    __syncthreads();
    const int w = threadIdx.x >> 5;
    if ((threadIdx.x & 31) == 0) { sRed[w] = a; sRed[16 + w] = b; }
    __syncthreads();
    float ra = 0.f, rb = 0.f;
#pragma unroll
    for (int i = 0; i < 16; i++) { ra += sRed[i]; rb += sRed[16 + i]; }
    a = ra; b = rb;
}

__global__ void zero_flags_kernel() {
    int t = threadIdx.x;
    if (t < NBLK) g_lineA[t][0] = 0u;
    if (t < BB)   g_lineB[t][0] = 0u;
    if (t == 0)   g_epochA = 0u;
}

// ====================================================================
__global__ void __launch_bounds__(NTHR, 1)
sgru_main(const float* __restrict__ x,       const float* __restrict__ h_in,
          const float* __restrict__ v_in,    const float* __restrict__ dU_in,
          const float* __restrict__ te_in,   const float* __restrict__ tE_in,
          const float* __restrict__ x2h_w,   const float* __restrict__ x2h_b,
          const float* __restrict__ h2h_w,   const float* __restrict__ h2h_b,
          const float* __restrict__ lnx_g,   const float* __restrict__ lnx_b,
          const float* __restrict__ lnh_g,   const float* __restrict__ lnh_b,
          const float* __restrict__ h2mod_w, const float* __restrict__ h2mod_b,
          const float* __restrict__ m2r_w,   const float* __restrict__ m2r_b,
          const float* __restrict__ m2s_w,   const float* __restrict__ m2s_b,
          const float* __restrict__ m2m_w,   const float* __restrict__ m2m_b,
          const float* __restrict__ alpha_p, const float* __restrict__ tauU_p,
          float* __restrict__ out)
{
    extern __shared__ float sm[];
    const int tid = threadIdx.x;
    const int bk  = blockIdx.x;
    const int wid = tid >> 5, lid = tid & 31;
    const int i0  = bk * 4;

    float* sWh   = sm + S_WH;
    float* sWx   = sm + S_WX;
    float* sH    = sm + S_H;
    float* sHfw  = sm + S_HFW;
    float* sTe   = sm + S_TE;
    float* sZW   = sm + S_ZW;
    float* sFwP  = sm + S_FWP;
    float* sMod  = sm + S_MOD;
    float* sScal = sm + S_SCAL;
    float* sRed  = sm + S_RED;
    float* sMu   = sm + S_MU;
    float* sRs   = sm + S_RS;
    float* sBt   = sm + S_BT;

    const float spa     = log1pf(expf(alpha_p[0]));
    const float inv_spe = 1.f / (spa + 1e-8f);
    const float tau     = 1.f / (1.f + expf(-tauU_p[0]));
    const float omtau   = 1.f - tau;

    // ================= PROLOGUE A: g_wx = LN(x @ x2h^T + b) =================
    {
        float* sX    = sm;           // [4][256]
        float* wtile = sm + 1024;    // [1536][9] padded
        const int rg0 = bk * 4;

        float acc[4][3];
#pragma unroll
        for (int r = 0; r < 4; r++)
#pragma unroll
            for (int q = 0; q < 3; q++) acc[r][q] = 0.f;

        for (int idx = tid; idx < 4 * IN_DIM; idx += NTHR)
            sX[idx] = x[(size_t)rg0 * IN_DIM + idx];

        for (int ct = 0; ct < 32; ++ct) {
            const int c0 = ct * 8;
            __syncthreads();
            for (int idx = tid; idx < H3 * 8; idx += NTHR) {
                int kl = idx >> 3, c = idx & 7;
                wtile[kl * 9 + c] = x2h_w[(size_t)kl * IN_DIM + c0 + c];
            }
            __syncthreads();
            float xv[4][8];
#pragma unroll
            for (int r = 0; r < 4; r++)
#pragma unroll
                for (int c = 0; c < 8; c++) xv[r][c] = sX[r * IN_DIM + c0 + c];
#pragma unroll
            for (int q = 0; q < 3; q++) {
                const int kk = tid + NTHR * q;
                float wv[8];
#pragma unroll
                for (int c = 0; c < 8; c++) wv[c] = wtile[kk * 9 + c];
#pragma unroll
                for (int r = 0; r < 4; r++)
#pragma unroll
                    for (int c = 0; c < 8; c++)
                        acc[r][q] = fmaf(wv[c], xv[r][c], acc[r][q]);
            }
        }
#pragma unroll
        for (int q = 0; q < 3; q++) {
            const float bq = x2h_b[tid + NTHR * q];
#pragma unroll
            for (int r = 0; r < 4; r++) acc[r][q] += bq;
        }
#pragma unroll
        for (int r = 0; r < 4; r++) {
            float s1 = 0.f, s2 = 0.f;
#pragma unroll
            for (int q = 0; q < 3; q++) { float v = acc[r][q]; s1 += v; s2 = fmaf(v, v, s2); }
            block_sum2(s1, s2, sRed);
            const float mu   = s1 * (1.f / H3);
            const float rstd = rsqrtf(s2 * (1.f / H3) - mu * mu + 1e-5f);
            float* wrow = g_wx + (size_t)(rg0 + r) * H3;
#pragma unroll
            for (int q = 0; q < 3; q++) {
                const int kk = tid + NTHR * q;
                wrow[kk] = (acc[r][q] - mu) * rstd * lnx_g[kk] + lnx_b[kk];
            }
        }
        __syncthreads();
    }

    // ================= PROLOGUE B: persistent state =================
    float rTE[32], rDU[32], vr[8], wrow[4], rUp[4], rLo[4], biasd[4];
#pragma unroll
    for (int il = 0; il < 4; ++il) {
        const float w = h2h_w[(size_t)(2 * HH + i0 + il) * HH + tid];
        wrow[il] = w;
        rUp[il]  =  fmaxf(1.f - w, 0.f) * inv_spe;
        rLo[il]  = -fmaxf(1.f + w, 0.f) * inv_spe;
        biasd[il] = h2h_b[2 * HH + i0 + il];
#pragma unroll
        for (int b = 0; b < 8; b++) {
            const int row = il * 8 + b;
            const size_t g = (size_t)(b * HH + i0 + il) * HH + tid;
            rTE[row] = tE_in[g];
            rDU[row] = dU_in[g];
        }
    }
    // zo weight rows into smem: rows bk*8 + w
    for (int idx = tid; idx < 8 * HH; idx += NTHR) {
        const int w = idx >> 9, j = idx & 511;
        sZW[idx] = h2h_w[(size_t)(bk * 8 + w) * HH + j];
    }
#pragma unroll
    for (int b = 0; b < 8; b++) {
        vr[b] = v_in[b * HH + tid];
        sTe[b * HH + tid] = te_in[b * HH + tid];
        sH [b * HH + tid] = h_in[b * HH + tid];
    }
    __syncthreads();

    // ================= MAIN LOOP =================
    for (int it = 0; it <= T_STEPS; ++it) {
        const bool last = (it == T_STEPS);

        // ---- Wx prefetch (safe for it>0: epoch sync of previous iter covers prologue) ----
        if (!last && it > 0) {
#pragma unroll
            for (int q = 0; q < 6; q++)
                __pipeline_memcpy_async(&((float4*)sWx)[tid + NTHR * q],
                                        &((const float4*)(g_wx + (size_t)it * (BB * H3)))[tid + NTHR * q], 16);
            __pipeline_commit();
        }

        // ---- zo GEMM (warps 0..7), off critical path ----
        if (!last) {
            float* whb = g_whbuf[it & 1];
            if (wid < 8) {
                const int k = bk * 8 + wid;
                float accA[8];
#pragma unroll
                for (int b = 0; b < 8; b++) accA[b] = 0.f;
#pragma unroll
                for (int c = 0; c < 4; c++) {
                    const float4 w4 = ((const float4*)&sZW[wid * HH])[lid + 32 * c];
#pragma unroll
                    for (int b = 0; b < 8; b++) {
                        const float4 h4 = ((const float4*)&sH[b * HH])[lid + 32 * c];
                        accA[b] += dot4(w4, h4);
                    }
                }
                const float bias = h2h_b[k];
#pragma unroll
                for (int b = 0; b < 8; b++) {
                    float v = wxor(accA[b]);
                    if (lid == b) __stcg(&whb[b * H3 + k], v + bias);
                }
            }
        }

        // ---- wait scalars (flagB) ----
        if (it > 0) {
            for (;;) {
                int ok = 1;
                if (tid < BB) ok = (ld_acq(&g_lineB[tid][0]) >= (unsigned)it);
                if (__syncthreads_count(ok) == NTHR) break;
            }
            if (tid < BB) {
                sScal[tid]      = __ldcg((const float*)&g_lineB[tid][1]);
                sScal[8 + tid]  = __ldcg((const float*)&g_lineB[tid][2]);
                sScal[16 + tid] = __ldcg((const float*)&g_lineB[tid][3]);
            }
            __syncthreads();
        }

        // ---- trace update (step it-1) fused with dv-row partial products ----
        float tnew[8];
#pragma unroll
        for (int b = 0; b < 8; b++) {
            const float hv = sH[b * HH + tid];
            float teo = 0.f, hf = 0.f, rb = 0.f, sb = 0.f, mb = 0.f;
            if (it > 0) {
                teo = sTe [b * HH + tid];
                hf  = sHfw[b * HH + tid];
                rb  = sScal[b]; sb = sScal[8 + b]; mb = sScal[16 + b];
            }
            const float oms = 1.f - sb;
            const float tm  = tau * mb;
#pragma unroll
            for (int il = 0; il < 4; ++il) {
                const int row = il * 8 + b;
                if (it > 0) {
                    const float hfi = sHfw[b * HH + i0 + il];
                    const float tei = sTe [b * HH + i0 + il];
                    const float t = oms * rTE[row] + sb * (hfi * teo - tei * hf);
                    rTE[row] = t;
                    float d = omtau * rDU[row] + tm * t;
                    d = fminf(d, rUp[il]);
                    d = fmaxf(d, rLo[il]);
                    rDU[row] = d;
                }
                if (!last) {
                    float p = (wrow[il] + spa * rDU[row]) * hv;
                    p = wred(p);
                    if (lid == 0) sFwP[row * 16 + wid] = p;
                }
            }
            if (it > 0) tnew[b] = (1.f - rb) * teo + rb * hf;
        }
        __syncthreads();
        if (it > 0) {
#pragma unroll
            for (int b = 0; b < 8; b++) sTe[b * HH + tid] = tnew[b];
        }

        if (!last) {
            float* whb = g_whbuf[it & 1];
            // combine dv partials: 512 threads, row=tid>>4, w=tid&15
            {
                float v = sFwP[(tid >> 4) * 16 + (tid & 15)];
#pragma unroll
                for (int o = 8; o; o >>= 1) v += __shfl_down_sync(0xffffffffu, v, o, 16);
                if ((tid & 15) == 0) {
                    const int row = tid >> 4, il = row >> 3, b = row & 7;
                    __stcg(&whb[b * H3 + 2 * HH + i0 + il], v + biasd[il]);
                }
            }
            // publish flagA
            __syncthreads();
            if (tid == 0) st_rel(&g_lineA[bk][0], (unsigned)(it + 1));

            // aggregator: block AGG scans 128 private lines, publishes epoch
            if (bk == AGG) {
                for (;;) {
                    int ok = 1;
                    if (tid < NBLK) ok = (ld_acq(&g_lineA[tid][0]) >= (unsigned)(it + 1));
                    if (__syncthreads_count(ok) == NTHR) break;
                }
                if (tid == 0) st_rel(&g_epochA, (unsigned)(it + 1));
            }

            // shadow: dUs(it-1) store
            if (it > 0) {
                float* dus = out + OUT_DUS + (size_t)(it - 1) * (BB * HH * HH);
#pragma unroll
                for (int il = 0; il < 4; ++il)
#pragma unroll
                    for (int b = 0; b < 8; b++)
                        __stcs(&dus[(size_t)(b * HH + i0 + il) * HH + tid], rDU[il * 8 + b]);
            }

            // wait epoch
            if (tid == 0) { while (ld_acq(&g_epochA) < (unsigned)(it + 1)) {} }
            __syncthreads();

            // it==0 Wx prefetch (only now is prologue globally complete)
            if (it == 0) {
#pragma unroll
                for (int q = 0; q < 6; q++)
                    __pipeline_memcpy_async(&((float4*)sWx)[tid + NTHR * q],
                                            &((const float4*)g_wx)[tid + NTHR * q], 16);
                __pipeline_commit();
            }

            // ---- Wh load fused with LN stats ----
            {
                const int b = tid >> 6, l6 = tid & 63;
                float s1 = 0.f, s2 = 0.f;
#pragma unroll
                for (int q = 0; q < 24; q++) {
                    const float v = __ldcg(&whb[b * H3 + l6 + 64 * q]);
                    sWh[b * H3 + l6 + 64 * q] = v;
                    s1 += v; s2 = fmaf(v, v, s2);
                }
#pragma unroll
                for (int o = 16; o; o >>= 1) {
                    s1 += __shfl_down_sync(0xffffffffu, s1, o);
                    s2 += __shfl_down_sync(0xffffffffu, s2, o);
                }
                if (lid == 0) { sRed[wid * 2] = s1; sRed[wid * 2 + 1] = s2; }
                __syncthreads();
                if (tid < 8) {
                    const float t1 = sRed[tid * 4] + sRed[tid * 4 + 2];
                    const float t2 = sRed[tid * 4 + 1] + sRed[tid * 4 + 3];
                    const float mu = t1 * (1.f / H3);
                    sMu[tid] = mu;
                    sRs[tid] = rsqrtf(t2 * (1.f / H3) - mu * mu + 1e-5f);
                }
                __pipeline_wait_prior(0);
                __syncthreads();
            }

            // ---- gates (redundant across blocks) ----
            {
                const float lg0 = lnh_g[tid],          lb0 = lnh_b[tid];
                const float lg1 = lnh_g[HH + tid],     lb1 = lnh_b[HH + tid];
                const float lg2 = lnh_g[2 * HH + tid], lb2 = lnh_b[2 * HH + tid];
#pragma unroll
                for (int b = 0; b < 8; b++) {
                    const float mu = sMu[b], rs = sRs[b];
                    const float pz = (sWh[b * H3 + tid]          - mu) * rs * lg0 + lb0 + sWx[b * H3 + tid];
                    const float po = (sWh[b * H3 + HH + tid]     - mu) * rs * lg1 + lb1 + sWx[b * H3 + HH + tid];
                    const float pd = (sWh[b * H3 + 2 * HH + tid] - mu) * rs * lg2 + lb2 + sWx[b * H3 + 2 * HH + tid];
                    const float z = sigm(pz);
                    const float o = sigm(po);
                    vr[b] = (1.f - z) * vr[b] + z * pd;
                    const float nh = fmaxf(vr[b], 0.f);
                    const float hf = o * nh;
                    sH  [b * HH + tid] = nh;
                    sHfw[b * HH + tid] = hf;
                    if (bk == 8 + b)
                        out[OUT_OUTS + (size_t)it * (BB * HH) + b * HH + tid] = nh;
                }
            }
            __syncthreads();

            // ---- batch phase: blocks 0..7 compute mod + scalars ----
            if (bk < BB) {
                const int b = bk;
                float4 n4[4];
#pragma unroll
                for (int c = 0; c < 4; c++)
                    n4[c] = ((const float4*)&sH[b * HH])[lid + 32 * c];
#pragma unroll
                for (int rr = 0; rr < 6; rr++) {
                    const int row = wid + 16 * rr;
                    const float4* mw = (const float4*)(h2mod_w + (size_t)row * HH);
                    float a = 0.f;
#pragma unroll
                    for (int c = 0; c < 4; c++) a += dot4(mw[lid + 32 * c], n4[c]);
                    a = wxor(a);
                    if (lid == 0) {
                        const float mv = fmaxf(a + h2mod_b[row], 0.f);
                        sMod[row] = mv;
                        out[OUT_MODS + (size_t)it * (BB * 96) + b * 96 + row] = mv;
                    }
                }
                __syncthreads();
                if (wid < 3) {
                    const float* ww = (wid == 0) ? m2r_w : (wid == 1) ? m2s_w : m2m_w;
                    float a = wxor(sMod[wid * 32 + lid] * ww[lid]);
                    if (lid == 0) {
                        if (wid == 0) {
                            const float r = sigm(a + m2r_b[0]);
                            sBt[0] = r;
                            out[OUT_RS + (size_t)it * BB + b] = r;
                        } else if (wid == 1) {
                            const float s = sigm(a + m2s_b[0]);
                            sBt[1] = s;
                            out[OUT_SS + (size_t)it * BB + b] = s;
                        } else {
                            const float mmv = a + m2m_b[0];
                            const float m = mmv - tanhf(mmv);
                            sBt[2] = m;
                            out[OUT_MS + (size_t)it * BB + b] = m;
                        }
                    }
                }
                __syncthreads();
                if (tid == 0) {
                    __stcg((float*)&g_lineB[b][1], sBt[0]);
                    __stcg((float*)&g_lineB[b][2], sBt[1]);
                    __stcg((float*)&g_lineB[b][3], sBt[2]);
                    st_rel(&g_lineB[b][0], (unsigned)(it + 1));
                }
            }
        }
    }

    // ================= EPILOGUE =================
    {
        float* dus63 = out + OUT_DUS + (size_t)(T_STEPS - 1) * (BB * HH * HH);
#pragma unroll
        for (int il = 0; il < 4; ++il)
#pragma unroll
            for (int b = 0; b < 8; b++) {
                const int row = il * 8 + b;
                const size_t g = (size_t)(b * HH + i0 + il) * HH + tid;
                dus63[g] = rDU[row];
                out[OUT_DUF + g]   = rDU[row];
                out[OUT_TEMAT + g] = rTE[row];
            }
    }
    if (bk < BB) {
        out[OUT_V   + bk * HH + tid] = vr[bk];
        out[OUT_H   + bk * HH + tid] = sH[bk * HH + tid];
        out[OUT_TEF + bk * HH + tid] = sTe[bk * HH + tid];
    }
}

// ====================================================================
extern "C" void kernel_launch(void* const* d_in, const int* in_sizes, int n_in,
                              void* d_out, int out_size) {
    const float* x       = (const float*)d_in[0];
    const float* h       = (const float*)d_in[1];
    const float* v       = (const float*)d_in[2];
    const float* dU      = (const float*)d_in[3];
    const float* te      = (const float*)d_in[4];
    const float* tE      = (const float*)d_in[5];
    const float* x2h_w   = (const float*)d_in[6];
    const float* x2h_b   = (const float*)d_in[7];
    const float* h2h_w   = (const float*)d_in[8];
    const float* h2h_b   = (const float*)d_in[9];
    const float* lnx_g   = (const float*)d_in[10];
    const float* lnx_b   = (const float*)d_in[11];
    const float* lnh_g   = (const float*)d_in[12];
    const float* lnh_b   = (const float*)d_in[13];
    const float* h2mod_w = (const float*)d_in[14];
    const float* h2mod_b = (const float*)d_in[15];
    const float* m2r_w   = (const float*)d_in[16];
    const float* m2r_b   = (const float*)d_in[17];
    const float* m2s_w   = (const float*)d_in[18];
    const float* m2s_b   = (const float*)d_in[19];
    const float* m2m_w   = (const float*)d_in[20];
    const float* m2m_b   = (const float*)d_in[21];
    const float* alpha   = (const float*)d_in[22];
    const float* tauU    = (const float*)d_in[23];
    float* out = (float*)d_out;

    const size_t smem = (size_t)SMEM_FLOATS * sizeof(float);
    cudaFuncSetAttribute(sgru_main, cudaFuncAttributeMaxDynamicSharedMemorySize, (int)smem);

    zero_flags_kernel<<<1, 128>>>();
    sgru_main<<<NBLK, NTHR, smem>>>(x, h, v, dU, te, tE,
                                    x2h_w, x2h_b, h2h_w, h2h_b,
                                    lnx_g, lnx_b, lnh_g, lnh_b,
                                    h2mod_w, h2mod_b,
                                    m2r_w, m2r_b, m2s_w, m2s_b, m2m_w, m2m_b,
                                    alpha, tauU, out);
}

// round 6
// speedup vs baseline: 1.4096x; 1.2191x over previous
#include <cuda_runtime.h>
#include <cstdint>

#define T_STEPS 64
#define BB      8
#define IN_DIM  256
#define HH      512
#define H3      1536
#define NBLK    128
#define NTHR    512
#define AGG     127
#define NSCAL   24

// ---------------- output offsets (floats) ----------------
#define OUT_V      0ull
#define OUT_H      4096ull
#define OUT_DUF    8192ull
#define OUT_TEF    2105344ull
#define OUT_TEMAT  2109440ull
#define OUT_OUTS   4206592ull
#define OUT_DUS    4468736ull
#define OUT_MODS   138686464ull
#define OUT_SS     138735616ull
#define OUT_MS     138736128ull
#define OUT_RS     138736640ull

// ---------------- smem layout (float index) ----------------
#define S_TEM  0        /* [32][512] trace_E matrix (float4 view) */
#define S_WH   16384    /* [8][1536] */
#define S_H    28672    /* [8][512]  */
#define S_HFW  32768    /* [8][512]  */
#define S_TE   36864    /* [8][512]  te vector */
#define S_ZW   40960    /* [8][512]  zo weight rows */
#define S_FWP  45056    /* [32][4]   */
#define S_MOD  45184    /* [32] pad 64 */
#define S_SCAL 45248    /* r[8] s[8] m[8] */
#define S_RED  45280    /* [32] */
#define S_MU   45312    /* [8] */
#define S_RS   45320    /* [8] */
#define SMEM_FLOATS 45328
// prologue overlay: sX [0,1024) + wtile [1024,14848) inside S_TEM

// ---------------- device globals ----------------
__device__ float    g_wx[T_STEPS * BB * H3];
__device__ float    g_whbuf[2][BB * H3];
__device__ unsigned g_lineA[NBLK][32];    // [0]=flag (128B padded)
__device__ unsigned g_lineB[NSCAL][32];   // [0]=flag, [1]=value bits
__device__ unsigned g_epochA;

// ---------------- helpers ----------------
__device__ __forceinline__ unsigned ld_acq(const unsigned* p) {
    unsigned v;
    asm volatile("ld.global.acquire.gpu.b32 %0, [%1];" : "=r"(v) : "l"(p) : "memory");
    return v;
}
__device__ __forceinline__ void st_rel(unsigned* p, unsigned v) {
    asm volatile("st.global.release.gpu.b32 [%0], %1;" :: "l"(p), "r"(v) : "memory");
}
__device__ __forceinline__ float sigm(float x) { return 1.f / (1.f + __expf(-x)); }
__device__ __forceinline__ float dot4(float4 a, float4 b) {
    return fmaf(a.x, b.x, fmaf(a.y, b.y, fmaf(a.z, b.z, a.w * b.w)));
}
__device__ __forceinline__ float wred(float v) {
#pragma unroll
    for (int o = 16; o; o >>= 1) v += __shfl_down_sync(0xffffffffu, v, o);
    return v;
}
__device__ __forceinline__ float wxor(float v) {
#pragma unroll
    for (int o = 16; o; o >>= 1) v += __shfl_xor_sync(0xffffffffu, v, o);
    return v;
}
__device__ __forceinline__ void block_sum2(float& a, float& b, float* sRed) {
#pragma unroll
    for (int o = 16; o; o >>= 1) {
        a += __shfl_down_sync(0xffffffffu, a, o);
        b += __shfl_down_sync(0xffffffffu, b, o);
    }
    __syncthreads();
    const int w = threadIdx.x >> 5;
    if ((threadIdx.x & 31) == 0) { sRed[w] = a; sRed[16 + w] = b; }
    __syncthreads();
    float ra = 0.f, rb = 0.f;
#pragma unroll
    for (int i = 0; i < 16; i++) { ra += sRed[i]; rb += sRed[16 + i]; }
    a = ra; b = rb;
}

__global__ void zero_flags_kernel() {
    int t = threadIdx.x;
    if (t < NBLK)  g_lineA[t][0] = 0u;
    if (t < NSCAL) g_lineB[t][0] = 0u;
    if (t == 0)    g_epochA = 0u;
}

// ====================================================================
__global__ void __launch_bounds__(NTHR, 1)
sgru_main(const float* __restrict__ x,       const float* __restrict__ h_in,
          const float* __restrict__ v_in,    const float* __restrict__ dU_in,
          const float* __restrict__ te_in,   const float* __restrict__ tE_in,
          const float* __restrict__ x2h_w,   const float* __restrict__ x2h_b,
          const float* __restrict__ h2h_w,   const float* __restrict__ h2h_b,
          const float* __restrict__ lnx_g,   const float* __restrict__ lnx_b,
          const float* __restrict__ lnh_g,   const float* __restrict__ lnh_b,
          const float* __restrict__ h2mod_w, const float* __restrict__ h2mod_b,
          const float* __restrict__ m2r_w,   const float* __restrict__ m2r_b,
          const float* __restrict__ m2s_w,   const float* __restrict__ m2s_b,
          const float* __restrict__ m2m_w,   const float* __restrict__ m2m_b,
          const float* __restrict__ alpha_p, const float* __restrict__ tauU_p,
          float* __restrict__ out)
{
    extern __shared__ float sm[];
    const int tid = threadIdx.x;
    const int bk  = blockIdx.x;
    const int wid = tid >> 5, lid = tid & 31;
    const int i0  = bk * 4;
    const int g   = tid >> 7;        // il group 0..3
    const int q   = tid & 127;       // quad index (j = 4q..4q+3)
    const int i   = i0 + g;          // this thread's i-row

    float*  sWh   = sm + S_WH;
    float*  sH    = sm + S_H;
    float*  sHfw  = sm + S_HFW;
    float*  sTe   = sm + S_TE;
    float*  sZW   = sm + S_ZW;
    float*  sFwP  = sm + S_FWP;
    float*  sMod  = sm + S_MOD;
    float*  sScal = sm + S_SCAL;
    float*  sRed  = sm + S_RED;
    float*  sMu   = sm + S_MU;
    float*  sRs   = sm + S_RS;
    float4* sTE4  = (float4*)(sm + S_TEM);
    float4* sH4   = (float4*)sH;
    float4* sHfw4 = (float4*)sHfw;
    float4* sTe4  = (float4*)sTe;

    const float spa     = log1pf(expf(alpha_p[0]));
    const float inv_spe = 1.f / (spa + 1e-8f);
    const float tau     = 1.f / (1.f + expf(-tauU_p[0]));
    const float omtau   = 1.f - tau;

    // ================= PROLOGUE A: g_wx = LN(x @ x2h^T + b) =================
    {
        float* sX    = sm;           // [4][256]
        float* wtile = sm + 1024;    // [1536][9] padded
        const int rg0 = bk * 4;

        float acc[4][3];
#pragma unroll
        for (int r = 0; r < 4; r++)
#pragma unroll
            for (int p = 0; p < 3; p++) acc[r][p] = 0.f;

        for (int idx = tid; idx < 4 * IN_DIM; idx += NTHR)
            sX[idx] = x[(size_t)rg0 * IN_DIM + idx];

        for (int ct = 0; ct < 32; ++ct) {
            const int c0 = ct * 8;
            __syncthreads();
            for (int idx = tid; idx < H3 * 8; idx += NTHR) {
                int kl = idx >> 3, c = idx & 7;
                wtile[kl * 9 + c] = x2h_w[(size_t)kl * IN_DIM + c0 + c];
            }
            __syncthreads();
            float xv[4][8];
#pragma unroll
            for (int r = 0; r < 4; r++)
#pragma unroll
                for (int c = 0; c < 8; c++) xv[r][c] = sX[r * IN_DIM + c0 + c];
#pragma unroll
            for (int p = 0; p < 3; p++) {
                const int kk = tid + NTHR * p;
                float wv[8];
#pragma unroll
                for (int c = 0; c < 8; c++) wv[c] = wtile[kk * 9 + c];
#pragma unroll
                for (int r = 0; r < 4; r++)
#pragma unroll
                    for (int c = 0; c < 8; c++)
                        acc[r][p] = fmaf(wv[c], xv[r][c], acc[r][p]);
            }
        }
#pragma unroll
        for (int p = 0; p < 3; p++) {
            const float bq = x2h_b[tid + NTHR * p];
#pragma unroll
            for (int r = 0; r < 4; r++) acc[r][p] += bq;
        }
#pragma unroll
        for (int r = 0; r < 4; r++) {
            float s1 = 0.f, s2 = 0.f;
#pragma unroll
            for (int p = 0; p < 3; p++) { float v = acc[r][p]; s1 += v; s2 = fmaf(v, v, s2); }
            block_sum2(s1, s2, sRed);
            const float mu   = s1 * (1.f / H3);
            const float rstd = rsqrtf(s2 * (1.f / H3) - mu * mu + 1e-5f);
            float* wrow = g_wx + (size_t)(rg0 + r) * H3;
#pragma unroll
            for (int p = 0; p < 3; p++) {
                const int kk = tid + NTHR * p;
                wrow[kk] = (acc[r][p] - mu) * rstd * lnx_g[kk] + lnx_b[kk];
            }
        }
        __syncthreads();
    }

    // ================= PROLOGUE B: persistent state =================
    float4 rDU4[8], w4, up4, lo4;
    float vr[8];
    {
        w4 = ((const float4*)(h2h_w + (size_t)(2 * HH + i) * HH))[q];
        up4.x =  fmaxf(1.f - w4.x, 0.f) * inv_spe;  lo4.x = -fmaxf(1.f + w4.x, 0.f) * inv_spe;
        up4.y =  fmaxf(1.f - w4.y, 0.f) * inv_spe;  lo4.y = -fmaxf(1.f + w4.y, 0.f) * inv_spe;
        up4.z =  fmaxf(1.f - w4.z, 0.f) * inv_spe;  lo4.z = -fmaxf(1.f + w4.z, 0.f) * inv_spe;
        up4.w =  fmaxf(1.f - w4.w, 0.f) * inv_spe;  lo4.w = -fmaxf(1.f + w4.w, 0.f) * inv_spe;
#pragma unroll
        for (int b = 0; b < 8; b++) {
            const size_t g4 = (size_t)(b * HH + i) * 128 + q;
            rDU4[b] = ((const float4*)dU_in)[g4];
            sTE4[(g * 8 + b) * 128 + q] = ((const float4*)tE_in)[g4];
        }
        for (int idx = tid; idx < 8 * HH; idx += NTHR) {
            const int w = idx >> 9, j = idx & 511;
            sZW[idx] = h2h_w[(size_t)(bk * 8 + w) * HH + j];
        }
#pragma unroll
        for (int b = 0; b < 8; b++) {
            vr[b] = v_in[b * HH + tid];
            sTe[b * HH + tid] = te_in[b * HH + tid];
            sH [b * HH + tid] = h_in[b * HH + tid];
        }
        __syncthreads();
    }

    // ================= MAIN LOOP =================
    for (int it = 0; it <= T_STEPS; ++it) {
        const bool last = (it == T_STEPS);
        float* whb = g_whbuf[it & 1];

        // ---- zo GEMM (warps 0..7): needs only local sH ----
        if (!last && wid < 8) {
            const int k = bk * 8 + wid;
            float accA[8];
#pragma unroll
            for (int b = 0; b < 8; b++) accA[b] = 0.f;
#pragma unroll
            for (int c = 0; c < 4; c++) {
                const float4 wv = ((const float4*)&sZW[wid * HH])[lid + 32 * c];
#pragma unroll
                for (int b = 0; b < 8; b++)
                    accA[b] += dot4(wv, sH4[b * 128 + lid + 32 * c]);
            }
            const float bias = h2h_b[k];
#pragma unroll
            for (int b = 0; b < 8; b++) {
                float v = wxor(accA[b]);
                if (lid == b) __stcg(&whb[b * H3 + k], v + bias);
            }
        }

        // ---- wait scalars (24 lines) ----
        if (it > 0) {
            for (;;) {
                int ok = 1;
                if (tid < NSCAL) ok = (ld_acq(&g_lineB[tid][0]) >= (unsigned)it);
                if (__syncthreads_count(ok) == NTHR) break;
            }
            if (tid < NSCAL) {
                const int b = tid & 7, sc = tid >> 3;
                sScal[sc * 8 + b] = __ldcg((const float*)&g_lineB[tid][1]);
            }
            __syncthreads();
        }

        // ---- trace update (step it-1) + fused dv partials ----
        float tnew[8];
#pragma unroll
        for (int b = 0; b < 8; b++) {
            if (it > 0) {
                const float rb  = sScal[b];
                const float sb  = sScal[8 + b];
                const float mb  = sScal[16 + b];
                const float oms = 1.f - sb;
                const float tm  = tau * mb;
                const float hfi = sHfw[b * HH + i];
                const float tei = sTe [b * HH + i];
                const float4 teo4 = sTe4 [b * 128 + q];
                const float4 hf4  = sHfw4[b * 128 + q];
                float4 t4 = sTE4[(g * 8 + b) * 128 + q];
                t4.x = oms * t4.x + sb * (hfi * teo4.x - tei * hf4.x);
                t4.y = oms * t4.y + sb * (hfi * teo4.y - tei * hf4.y);
                t4.z = oms * t4.z + sb * (hfi * teo4.z - tei * hf4.z);
                t4.w = oms * t4.w + sb * (hfi * teo4.w - tei * hf4.w);
                sTE4[(g * 8 + b) * 128 + q] = t4;
                float4 d4 = rDU4[b];
                d4.x = fmaxf(fminf(omtau * d4.x + tm * t4.x, up4.x), lo4.x);
                d4.y = fmaxf(fminf(omtau * d4.y + tm * t4.y, up4.y), lo4.y);
                d4.z = fmaxf(fminf(omtau * d4.z + tm * t4.z, up4.z), lo4.z);
                d4.w = fmaxf(fminf(omtau * d4.w + tm * t4.w, up4.w), lo4.w);
                rDU4[b] = d4;
                tnew[b] = (1.f - rb) * sTe[b * HH + tid] + rb * sHfw[b * HH + tid];
            }
            if (!last) {
                const float4 h4 = sH4[b * 128 + q];
                const float4 d4 = rDU4[b];
                float p = (w4.x + spa * d4.x) * h4.x;
                p = fmaf(w4.y + spa * d4.y, h4.y, p);
                p = fmaf(w4.z + spa * d4.z, h4.z, p);
                p = fmaf(w4.w + spa * d4.w, h4.w, p);
                p = wred(p);
                if (lid == 0) sFwP[(g * 8 + b) * 4 + (wid & 3)] = p;
            }
        }
        __syncthreads();
        if (it > 0) {
#pragma unroll
            for (int b = 0; b < 8; b++) sTe[b * HH + tid] = tnew[b];
        }

        if (last) break;

        // ---- dv combine + flagA publish ----
        if (tid < 32) {
            const float v = sFwP[tid * 4] + sFwP[tid * 4 + 1] + sFwP[tid * 4 + 2] + sFwP[tid * 4 + 3];
            const int b = tid & 7, gg = tid >> 3;
            const int k = 2 * HH + i0 + gg;
            __stcg(&whb[b * H3 + k], v + h2h_b[k]);
        }
        __syncthreads();
        if (tid == 0) st_rel(&g_lineA[bk][0], (unsigned)(it + 1));

        // aggregator double-hop
        if (bk == AGG) {
            for (;;) {
                int ok = 1;
                if (tid < NBLK) ok = (ld_acq(&g_lineA[tid][0]) >= (unsigned)(it + 1));
                if (__syncthreads_count(ok) == NTHR) break;
            }
            if (tid == 0) st_rel(&g_epochA, (unsigned)(it + 1));
        }

        // shadow: dUs(it-1) store (float4, coalesced)
        if (it > 0) {
            float4* dus4 = (float4*)(out + OUT_DUS + (size_t)(it - 1) * (BB * HH * HH));
#pragma unroll
            for (int b = 0; b < 8; b++)
                __stcs(&dus4[(size_t)(b * HH + i) * 128 + q], rDU4[b]);
        }

        // wait epoch
        if (tid == 0) { while (ld_acq(&g_epochA) < (unsigned)(it + 1)) {} }
        __syncthreads();

        // ---- Wh load fused with LN stats ----
        {
            const int b = tid >> 6, l6 = tid & 63;
            float s1 = 0.f, s2 = 0.f;
#pragma unroll
            for (int p = 0; p < 24; p++) {
                const float v = __ldcg(&whb[b * H3 + l6 + 64 * p]);
                sWh[b * H3 + l6 + 64 * p] = v;
                s1 += v; s2 = fmaf(v, v, s2);
            }
#pragma unroll
            for (int o = 16; o; o >>= 1) {
                s1 += __shfl_down_sync(0xffffffffu, s1, o);
                s2 += __shfl_down_sync(0xffffffffu, s2, o);
            }
            if (lid == 0) { sRed[wid * 2] = s1; sRed[wid * 2 + 1] = s2; }
            __syncthreads();
            if (tid < 8) {
                const float t1 = sRed[tid * 4] + sRed[tid * 4 + 2];
                const float t2 = sRed[tid * 4 + 1] + sRed[tid * 4 + 3];
                const float mu = t1 * (1.f / H3);
                sMu[tid] = mu;
                sRs[tid] = rsqrtf(t2 * (1.f / H3) - mu * mu + 1e-5f);
            }
            __syncthreads();
        }

        // ---- gates (redundant across blocks) ----
        {
            const float lg0 = lnh_g[tid],          lb0 = lnh_b[tid];
            const float lg1 = lnh_g[HH + tid],     lb1 = lnh_b[HH + tid];
            const float lg2 = lnh_g[2 * HH + tid], lb2 = lnh_b[2 * HH + tid];
            const float* wxg = g_wx + (size_t)it * (BB * H3);
#pragma unroll
            for (int b = 0; b < 8; b++) {
                const float mu = sMu[b], rs = sRs[b];
                const float wx0 = __ldcg(&wxg[b * H3 + tid]);
                const float wx1 = __ldcg(&wxg[b * H3 + HH + tid]);
                const float wx2 = __ldcg(&wxg[b * H3 + 2 * HH + tid]);
                const float pz = (sWh[b * H3 + tid]          - mu) * rs * lg0 + lb0 + wx0;
                const float po = (sWh[b * H3 + HH + tid]     - mu) * rs * lg1 + lb1 + wx1;
                const float pd = (sWh[b * H3 + 2 * HH + tid] - mu) * rs * lg2 + lb2 + wx2;
                const float z = sigm(pz);
                const float o = sigm(po);
                vr[b] = (1.f - z) * vr[b] + z * pd;
                const float nh = fmaxf(vr[b], 0.f);
                const float hf = o * nh;
                sH  [b * HH + tid] = nh;
                sHfw[b * HH + tid] = hf;
                if (bk == 32 + b)
                    out[OUT_OUTS + (size_t)it * (BB * HH) + b * HH + tid] = nh;
            }
        }
        __syncthreads();

        // ---- scalar blocks (0..23): 32 mod rows + one scalar each ----
        if (bk < NSCAL) {
            const int b  = bk & 7;
            const int sc = bk >> 3;        // 0=r, 1=s, 2=m
            const int r0 = sc * 32;
            // mod rows r0..r0+31: 16 warps x 2 rows
#pragma unroll
            for (int rr = 0; rr < 2; rr++) {
                const int rl  = wid * 2 + rr;
                const int row = r0 + rl;
                const float4* mw = (const float4*)(h2mod_w + (size_t)row * HH);
                float a = 0.f;
#pragma unroll
                for (int c = 0; c < 4; c++)
                    a += dot4(mw[lid + 32 * c], sH4[b * 128 + lid + 32 * c]);
                a = wxor(a);
                if (lid == 0) {
                    const float mv = fmaxf(a + h2mod_b[row], 0.f);
                    sMod[rl] = mv;
                    out[OUT_MODS + (size_t)it * (BB * 96) + b * 96 + row] = mv;
                }
            }
            __syncthreads();
            if (wid == 0) {
                const float* ww = (sc == 0) ? m2r_w : (sc == 1) ? m2s_w : m2m_w;
                float a = wxor(sMod[lid] * ww[lid]);
                if (lid == 0) {
                    float val;
                    if (sc == 0) {
                        val = sigm(a + m2r_b[0]);
                        out[OUT_RS + (size_t)it * BB + b] = val;
                    } else if (sc == 1) {
                        val = sigm(a + m2s_b[0]);
                        out[OUT_SS + (size_t)it * BB + b] = val;
                    } else {
                        const float mm = a + m2m_b[0];
                        val = mm - tanhf(mm);
                        out[OUT_MS + (size_t)it * BB + b] = val;
                    }
                    __stcg((float*)&g_lineB[bk][1], val);
                    st_rel(&g_lineB[bk][0], (unsigned)(it + 1));
                }
            }
        }
    }

    // ================= EPILOGUE =================
    {
        float4* dus4 = (float4*)(out + OUT_DUS + (size_t)(T_STEPS - 1) * (BB * HH * HH));
        float4* duf4 = (float4*)(out + OUT_DUF);
        float4* tem4 = (float4*)(out + OUT_TEMAT);
#pragma unroll
        for (int b = 0; b < 8; b++) {
            const size_t g4 = (size_t)(b * HH + i) * 128 + q;
            dus4[g4] = rDU4[b];
            duf4[g4] = rDU4[b];
            tem4[g4] = sTE4[(g * 8 + b) * 128 + q];
        }
    }
    if (bk < BB) {
        out[OUT_V   + bk * HH + tid] = vr[bk];
        out[OUT_H   + bk * HH + tid] = sH[bk * HH + tid];
        out[OUT_TEF + bk * HH + tid] = sTe[bk * HH + tid];
    }
}

// ====================================================================
extern "C" void kernel_launch(void* const* d_in, const int* in_sizes, int n_in,
                              void* d_out, int out_size) {
    const float* x       = (const float*)d_in[0];
    const float* h       = (const float*)d_in[1];
    const float* v       = (const float*)d_in[2];
    const float* dU      = (const float*)d_in[3];
    const float* te      = (const float*)d_in[4];
    const float* tE      = (const float*)d_in[5];
    const float* x2h_w   = (const float*)d_in[6];
    const float* x2h_b   = (const float*)d_in[7];
    const float* h2h_w   = (const float*)d_in[8];
    const float* h2h_b   = (const float*)d_in[9];
    const float* lnx_g   = (const float*)d_in[10];
    const float* lnx_b   = (const float*)d_in[11];
    const float* lnh_g   = (const float*)d_in[12];
    const float* lnh_b   = (const float*)d_in[13];
    const float* h2mod_w = (const float*)d_in[14];
    const float* h2mod_b = (const float*)d_in[15];
    const float* m2r_w   = (const float*)d_in[16];
    const float* m2r_b   = (const float*)d_in[17];
    const float* m2s_w   = (const float*)d_in[18];
    const float* m2s_b   = (const float*)d_in[19];
    const float* m2m_w   = (const float*)d_in[20];
    const float* m2m_b   = (const float*)d_in[21];
    const float* alpha   = (const float*)d_in[22];
    const float* tauU    = (const float*)d_in[23];
    float* out = (float*)d_out;

    const size_t smem = (size_t)SMEM_FLOATS * sizeof(float);
    cudaFuncSetAttribute(sgru_main, cudaFuncAttributeMaxDynamicSharedMemorySize, (int)smem);

    zero_flags_kernel<<<1, 128>>>();
    sgru_main<<<NBLK, NTHR, smem>>>(x, h, v, dU, te, tE,
                                    x2h_w, x2h_b, h2h_w, h2h_b,
                                    lnx_g, lnx_b, lnh_g, lnh_b,
                                    h2mod_w, h2mod_b,
                                    m2r_w, m2r_b, m2s_w, m2s_b, m2m_w, m2m_b,
                                    alpha, tauU, out);
}